// round 1
// baseline (speedup 1.0000x reference)
#include <cuda_runtime.h>
#include <math.h>

#define BNUM 16
#define LNUM 20
#define CNUM 256
#define DT   768

// ---------------- scratch (static device globals; no allocation) ----------------
__device__ float g_K[BNUM*LNUM*CNUM];
__device__ float g_V[BNUM*LNUM*CNUM];
__device__ float g_M[BNUM*LNUM*CNUM];
__device__ float g_scale[BNUM*CNUM];   // 1 + gamma
__device__ float g_beta[BNUM*CNUM];
__device__ float g_vec2[BNUM*2];
__device__ int   g_maxbuf[64];         // per (level,b) max gate, float bits
__device__ __align__(16) float g_gate_raw[348160];
__device__ __align__(16) float g_gi[348160];

// ---------------- per-level constants ----------------
__constant__ int   c_HW[4]      = {16384, 4096, 1024, 256};
__constant__ int   c_W[4]       = {128, 64, 32, 16};
__constant__ int   c_lw[4]      = {7, 6, 5, 4};
__constant__ int   c_lHW4[4]    = {12, 10, 8, 6};           // log2(HW/4)
__constant__ int   c_pixBase[4] = {0, 262144, 327680, 344064};
__constant__ int   c_gateOut[4] = {89128960, 89391104, 89456640, 89473024};
__constant__ float c_step[4]    = {2.f/127.f, 2.f/63.f, 2.f/31.f, 2.f/15.f};

// ---------------- packed f32x2 helpers (Blackwell FFMA2) ----------------
__device__ __forceinline__ unsigned long long pk2(float lo, float hi) {
    unsigned long long r;
    asm("mov.b64 %0,{%1,%2};" : "=l"(r) : "f"(lo), "f"(hi));
    return r;
}
__device__ __forceinline__ void fma2(unsigned long long& d, unsigned long long a, unsigned long long b) {
    asm("fma.rn.f32x2 %0,%1,%2,%0;" : "+l"(d) : "l"(a), "l"(b));
}
__device__ __forceinline__ float2 unpk2(unsigned long long v) {
    float2 f;
    asm("mov.b64 {%0,%1},%2;" : "=f"(f.x), "=f"(f.y) : "l"(v));
    return f;
}

// ---------------- P1: K = wt@Wk, V = wt@Wv; zero maxbuf ----------------
__global__ void kv_kernel(const float* __restrict__ wt,
                          const float* __restrict__ Wk,
                          const float* __restrict__ Wv) {
    int bl = blockIdx.x;          // 0..319 = b*20+l
    int c  = threadIdx.x;         // 0..255
    if (bl == 0 && c < 64) g_maxbuf[c] = 0;
    const float* w = wt + (size_t)bl * DT;
    float ak = 0.f, av = 0.f;
    for (int d = 0; d < DT; ++d) {
        float x = __ldg(&w[d]);
        ak = fmaf(x, Wk[d*CNUM + c], ak);
        av = fmaf(x, Wv[d*CNUM + c], av);
    }
    g_K[bl*CNUM + c] = ak;
    g_V[bl*CNUM + c] = av;
}

// ---------------- P2: M = (K @ Wq) / sqrt(C)  (Wq stored [o,c]) ----------------
__global__ void m_kernel(const float* __restrict__ Wq) {
    __shared__ float sK[CNUM];
    int bl = blockIdx.x, c = threadIdx.x;
    sK[c] = g_K[bl*CNUM + c];
    __syncthreads();
    float a = 0.f;
    for (int o = 0; o < CNUM; ++o)
        a = fmaf(sK[o], Wq[o*CNUM + c], a);
    g_M[bl*CNUM + c] = a * 0.0625f;   // 1/sqrt(256)
}

// ---------------- P3: gamma/beta/vec2 MLPs from sent_vec ----------------
__global__ void mod_kernel(const float* __restrict__ sent,
                           const float* __restrict__ gw1, const float* __restrict__ gb1,
                           const float* __restrict__ gw2, const float* __restrict__ gb2,
                           const float* __restrict__ bw1, const float* __restrict__ bb1,
                           const float* __restrict__ bw2, const float* __restrict__ bb2,
                           const float* __restrict__ dw1, const float* __restrict__ db1,
                           const float* __restrict__ dw2, const float* __restrict__ db2) {
    __shared__ float sh[CNUM];
    __shared__ float ss[DT];
    int b = blockIdx.x, t = threadIdx.x;
    for (int i = t; i < DT; i += 256) ss[i] = sent[b*DT + i];
    __syncthreads();
    // gamma -> scale = 1 + gamma
    float a = gb1[t];
    for (int d = 0; d < DT; ++d) a = fmaf(ss[d], gw1[d*CNUM + t], a);
    sh[t] = fmaxf(a, 0.f);
    __syncthreads();
    float g = gb2[t];
    for (int j = 0; j < CNUM; ++j) g = fmaf(sh[j], gw2[j*CNUM + t], g);
    g_scale[b*CNUM + t] = 1.f + g;
    __syncthreads();
    // beta
    a = bb1[t];
    for (int d = 0; d < DT; ++d) a = fmaf(ss[d], bw1[d*CNUM + t], a);
    sh[t] = fmaxf(a, 0.f);
    __syncthreads();
    g = bb2[t];
    for (int j = 0; j < CNUM; ++j) g = fmaf(sh[j], bw2[j*CNUM + t], g);
    g_beta[b*CNUM + t] = g;
    __syncthreads();
    // vec2 (direction)
    if (t < 64) {
        a = db1[t];
        for (int d = 0; d < DT; ++d) a = fmaf(ss[d], dw1[d*64 + t], a);
        sh[t] = fmaxf(a, 0.f);
    }
    __syncthreads();
    if (t == 0) {
        float v0 = db2[0], v1 = db2[1];
        for (int j = 0; j < 64; ++j) {
            v0 = fmaf(sh[j], dw2[j*2 + 0], v0);
            v1 = fmaf(sh[j], dw2[j*2 + 1], v1);
        }
        float nrm = fmaxf(sqrtf(v0*v0 + v1*v1), 1e-12f);
        g_vec2[b*2 + 0] = v0 / nrm;
        g_vec2[b*2 + 1] = v1 / nrm;
    }
}

// ---------------- helper: block -> (level, b, tile) ----------------
__device__ __forceinline__ void decode_block(int bid, int& level, int& b, int& tile) {
    if (bid < 1024)      { level = 0; b = bid >> 6; tile = bid & 63; }
    else if (bid < 1280) { int r = bid - 1024; level = 1; b = r >> 4; tile = r & 15; }
    else if (bid < 1344) { int r = bid - 1280; level = 2; b = r >> 2; tile = r & 3; }
    else                 { level = 3; b = bid - 1344; tile = 0; }
}

// ---------------- Phase A: per-pixel attention gate (raw) ----------------
__global__ __launch_bounds__(256) void phaseA(const float* __restrict__ f0,
                                              const float* __restrict__ f1,
                                              const float* __restrict__ f2,
                                              const float* __restrict__ f3,
                                              const int* __restrict__ mask) {
    __shared__ __align__(16) float sM[LNUM*CNUM];
    __shared__ __align__(16) float sV[LNUM*CNUM];
    __shared__ int smask[LNUM];

    int level, b, tile;
    decode_block(blockIdx.x, level, b, tile);
    int t = threadIdx.x;
    int bbase = b * LNUM * CNUM;
    for (int i = t; i < LNUM*CNUM; i += 256) {
        sM[i] = g_M[bbase + i];
        sV[i] = g_V[bbase + i];
    }
    if (t < LNUM) smask[t] = mask[b*LNUM + t];
    __syncthreads();

    const int HW = c_HW[level];
    int n = tile * 256 + t;
    const float* fp = (level == 0) ? f0 : (level == 1) ? f1 : (level == 2) ? f2 : f3;
    fp += (size_t)(b * CNUM) * HW + n;

    // logits[l] = sum_c f[c] * M[l,c]   (packed f32x2)
    unsigned long long acc[LNUM];
#pragma unroll
    for (int l = 0; l < LNUM; ++l) acc[l] = 0ull;

    for (int c = 0; c < CNUM; c += 4) {
        float a0 = fp[(size_t)(c+0)*HW];
        float a1 = fp[(size_t)(c+1)*HW];
        float a2 = fp[(size_t)(c+2)*HW];
        float a3 = fp[(size_t)(c+3)*HW];
        unsigned long long fv01 = pk2(a0, a1);
        unsigned long long fv23 = pk2(a2, a3);
#pragma unroll
        for (int l = 0; l < LNUM; ++l) {
            const ulonglong2 m = *reinterpret_cast<const ulonglong2*>(&sM[l*CNUM + c]);
            fma2(acc[l], fv01, m.x);
            fma2(acc[l], fv23, m.y);
        }
    }
    float lg[LNUM];
#pragma unroll
    for (int l = 0; l < LNUM; ++l) { float2 u = unpk2(acc[l]); lg[l] = u.x + u.y; }

    // masked softmax over L=20
    float mx = -1e30f;
#pragma unroll
    for (int l = 0; l < LNUM; ++l) if (smask[l]) mx = fmaxf(mx, lg[l]);
    float s = 0.f;
#pragma unroll
    for (int l = 0; l < LNUM; ++l) {
        float e = smask[l] ? __expf(lg[l] - mx) : 0.f;
        lg[l] = e; s += e;
    }
    float inv = __fdividef(1.f, s);
    unsigned long long at2[LNUM];
#pragma unroll
    for (int l = 0; l < LNUM; ++l) { float a = lg[l] * inv; at2[l] = pk2(a, a); }

    // gate = || attn @ V ||_2 over C
    float gsq = 0.f;
    for (int c = 0; c < CNUM; c += 4) {
        unsigned long long g01 = 0ull, g23 = 0ull;
#pragma unroll
        for (int l = 0; l < LNUM; ++l) {
            const ulonglong2 v = *reinterpret_cast<const ulonglong2*>(&sV[l*CNUM + c]);
            fma2(g01, at2[l], v.x);
            fma2(g23, at2[l], v.y);
        }
        float2 u = unpk2(g01), w2 = unpk2(g23);
        gsq = fmaf(u.x, u.x, gsq);  gsq = fmaf(u.y, u.y, gsq);
        gsq = fmaf(w2.x, w2.x, gsq); gsq = fmaf(w2.y, w2.y, gsq);
    }
    float gate = sqrtf(gsq);
    g_gate_raw[c_pixBase[level] + b*HW + n] = gate;
    atomicMax(&g_maxbuf[level*16 + b], __float_as_int(gate));   // gate >= 0
}

// ---------------- Phase A2: gi = gate/(max+eps) * sigmoid(dir); write gate outputs ----------------
__global__ void phaseA2(float* __restrict__ out) {
    int level, b, tile;
    decode_block(blockIdx.x, level, b, tile);
    int t = threadIdx.x;
    const int HW = c_HW[level];
    const int W  = c_W[level];
    const int lw = c_lw[level];
    int n = tile * 256 + t;
    int w = n & (W - 1);
    int h = n >> lw;
    float step = c_step[level];               // H == W for all levels
    float x = fmaf((float)w, step, -1.f);
    float y = fmaf((float)h, step, -1.f);
    float v0 = g_vec2[2*b], v1 = g_vec2[2*b + 1];
    float p  = v0 * x + v1 * y;
    float di = __fdividef(1.f, 1.f + __expf(-p));
    float mxv = __int_as_float(g_maxbuf[level*16 + b]);
    float gate = g_gate_raw[c_pixBase[level] + b*HW + n];
    float gi = __fdividef(gate, mxv + 1e-6f) * di;
    g_gi[c_pixBase[level] + b*HW + n] = gi;
    out[c_gateOut[level] + b*HW + n] = gi;
}

// ---------------- Phase B: mods = gi * F * scale + beta (float4 streams) ----------------
__global__ __launch_bounds__(256) void phaseB(const float* __restrict__ f0,
                                              const float* __restrict__ f1,
                                              const float* __restrict__ f2,
                                              const float* __restrict__ f3,
                                              float* __restrict__ out) {
    int g4 = blockIdx.x * 256 + threadIdx.x;      // float4 index over mod region
    int level, idx;
    if (g4 < 16777216)      { level = 0; idx = g4; }
    else if (g4 < 20971520) { level = 1; idx = g4 - 16777216; }
    else if (g4 < 22020096) { level = 2; idx = g4 - 20971520; }
    else                    { level = 3; idx = g4 - 22020096; }
    const int HW    = c_HW[level];
    const int lHW4  = c_lHW4[level];
    int n4   = idx & ((HW >> 2) - 1);
    int rest = idx >> lHW4;
    int c = rest & 255;
    int b = rest >> 8;
    int n = n4 << 2;

    const float* fp = (level == 0) ? f0 : (level == 1) ? f1 : (level == 2) ? f2 : f3;
    const float4 f  = *reinterpret_cast<const float4*>(fp + (size_t)(b*CNUM + c)*HW + n);
    const float4 gi = *reinterpret_cast<const float4*>(&g_gi[c_pixBase[level] + b*HW + n]);
    float sc = g_scale[b*CNUM + c];
    float be = g_beta[b*CNUM + c];
    float4 o;
    o.x = fmaf(gi.x * f.x, sc, be);
    o.y = fmaf(gi.y * f.y, sc, be);
    o.z = fmaf(gi.z * f.z, sc, be);
    o.w = fmaf(gi.w * f.w, sc, be);
    *reinterpret_cast<float4*>(out + (size_t)g4 * 4) = o;
}

// ---------------- launch ----------------
extern "C" void kernel_launch(void* const* d_in, const int* in_sizes, int n_in,
                              void* d_out, int out_size) {
    const float* f0   = (const float*)d_in[0];
    const float* f1   = (const float*)d_in[1];
    const float* f2   = (const float*)d_in[2];
    const float* f3   = (const float*)d_in[3];
    const float* wt   = (const float*)d_in[4];
    const float* sent = (const float*)d_in[5];
    const int*   mask = (const int*)  d_in[6];
    const float* Wq   = (const float*)d_in[7];
    const float* Wk   = (const float*)d_in[8];
    const float* Wv   = (const float*)d_in[9];
    const float* gw1  = (const float*)d_in[10];
    const float* gb1  = (const float*)d_in[11];
    const float* gw2  = (const float*)d_in[12];
    const float* gb2  = (const float*)d_in[13];
    const float* bw1  = (const float*)d_in[14];
    const float* bb1  = (const float*)d_in[15];
    const float* bw2  = (const float*)d_in[16];
    const float* bb2  = (const float*)d_in[17];
    const float* dw1  = (const float*)d_in[18];
    const float* db1  = (const float*)d_in[19];
    const float* dw2  = (const float*)d_in[20];
    const float* db2  = (const float*)d_in[21];
    float* out = (float*)d_out;

    kv_kernel<<<BNUM*LNUM, 256>>>(wt, Wk, Wv);
    m_kernel<<<BNUM*LNUM, 256>>>(Wq);
    mod_kernel<<<BNUM, 256>>>(sent, gw1, gb1, gw2, gb2, bw1, bb1, bw2, bb2,
                              dw1, db1, dw2, db2);
    phaseA<<<1360, 256>>>(f0, f1, f2, f3, mask);
    phaseA2<<<1360, 256>>>(out);
    phaseB<<<87040, 256>>>(f0, f1, f2, f3, out);
}

// round 2
// speedup vs baseline: 1.1347x; 1.1347x over previous
#include <cuda_runtime.h>
#include <math.h>

#define BNUM 16
#define LNUM 20
#define CNUM 256
#define DT   768

// ---------------- scratch ----------------
__device__ float g_K[BNUM*LNUM*CNUM];
__device__ float g_V[BNUM*LNUM*CNUM];
__device__ float g_M[BNUM*LNUM*CNUM];
__device__ float g_scale[BNUM*CNUM];
__device__ float g_beta[BNUM*CNUM];
__device__ float g_vec2[BNUM*2];
__device__ int   g_maxbuf[64];
__device__ __align__(16) float g_gate_raw[348160];
__device__ __align__(16) float g_gi[348160];

// ---------------- per-level constants ----------------
__constant__ int   c_HW[4]      = {16384, 4096, 1024, 256};
__constant__ int   c_W[4]       = {128, 64, 32, 16};
__constant__ int   c_lw[4]      = {7, 6, 5, 4};
__constant__ int   c_lHW4[4]    = {12, 10, 8, 6};
__constant__ int   c_pixBase[4] = {0, 262144, 327680, 344064};
__constant__ int   c_gateOut[4] = {89128960, 89391104, 89456640, 89473024};
__constant__ float c_step[4]    = {2.f/127.f, 2.f/63.f, 2.f/31.f, 2.f/15.f};

// ---------------- packed f32x2 helpers ----------------
__device__ __forceinline__ unsigned long long pk2(float lo, float hi) {
    unsigned long long r;
    asm("mov.b64 %0,{%1,%2};" : "=l"(r) : "f"(lo), "f"(hi));
    return r;
}
__device__ __forceinline__ void fma2(unsigned long long& d, unsigned long long a, unsigned long long b) {
    asm("fma.rn.f32x2 %0,%1,%2,%0;" : "+l"(d) : "l"(a), "l"(b));
}
__device__ __forceinline__ float2 unpk2(unsigned long long v) {
    float2 f;
    asm("mov.b64 {%0,%1},%2;" : "=f"(f.x), "=f"(f.y) : "l"(v));
    return f;
}

// ================= prep: blocks 0..39 = KV tiles (8 rows each); 40..55 = mod MLPs =================
#define KV_ROWS 8
__global__ __launch_bounds__(256) void prep_kernel(
    const float* __restrict__ wt, const float* __restrict__ Wk, const float* __restrict__ Wv,
    const float* __restrict__ sent,
    const float* __restrict__ gw1, const float* __restrict__ gb1,
    const float* __restrict__ gw2, const float* __restrict__ gb2,
    const float* __restrict__ bw1, const float* __restrict__ bb1,
    const float* __restrict__ bw2, const float* __restrict__ bb2,
    const float* __restrict__ dw1, const float* __restrict__ db1,
    const float* __restrict__ dw2, const float* __restrict__ db2)
{
    __shared__ __align__(16) float swt[KV_ROWS*DT];   // kv path (24KB)
    __shared__ __align__(16) float ss[DT];            // mod path
    __shared__ float sh[CNUM];
    int t = threadIdx.x;
    int bid = blockIdx.x;

    if (bid < 40) {
        // ---- KV: rows [bid*8, bid*8+8) of (b*l), all 256 columns ----
        if (bid == 0 && t < 64) g_maxbuf[t] = 0;
        int r0 = bid * KV_ROWS;
        for (int i = t; i < KV_ROWS*DT; i += 256) swt[i] = wt[(size_t)r0*DT + i];
        __syncthreads();
        float aK[KV_ROWS], aV[KV_ROWS];
#pragma unroll
        for (int r = 0; r < KV_ROWS; ++r) { aK[r] = 0.f; aV[r] = 0.f; }
        int c = t;
        for (int d = 0; d < DT; d += 4) {
            float k0 = Wk[(d+0)*CNUM + c], k1 = Wk[(d+1)*CNUM + c];
            float k2 = Wk[(d+2)*CNUM + c], k3 = Wk[(d+3)*CNUM + c];
            float v0 = Wv[(d+0)*CNUM + c], v1 = Wv[(d+1)*CNUM + c];
            float v2 = Wv[(d+2)*CNUM + c], v3 = Wv[(d+3)*CNUM + c];
#pragma unroll
            for (int r = 0; r < KV_ROWS; ++r) {
                float4 w = *reinterpret_cast<const float4*>(&swt[r*DT + d]);
                aK[r] = fmaf(w.x, k0, aK[r]); aK[r] = fmaf(w.y, k1, aK[r]);
                aK[r] = fmaf(w.z, k2, aK[r]); aK[r] = fmaf(w.w, k3, aK[r]);
                aV[r] = fmaf(w.x, v0, aV[r]); aV[r] = fmaf(w.y, v1, aV[r]);
                aV[r] = fmaf(w.z, v2, aV[r]); aV[r] = fmaf(w.w, v3, aV[r]);
            }
        }
#pragma unroll
        for (int r = 0; r < KV_ROWS; ++r) {
            g_K[(r0 + r)*CNUM + c] = aK[r];
            g_V[(r0 + r)*CNUM + c] = aV[r];
        }
    } else {
        // ---- mod MLPs for batch b ----
        int b = bid - 40;
        for (int i = t; i < DT; i += 256) ss[i] = sent[b*DT + i];
        __syncthreads();
        // gamma
        {
            float a0=0,a1=0,a2=0,a3=0;
            for (int d = 0; d < DT; d += 4) {
                float4 s = *reinterpret_cast<const float4*>(&ss[d]);
                a0 = fmaf(s.x, gw1[(d+0)*CNUM + t], a0);
                a1 = fmaf(s.y, gw1[(d+1)*CNUM + t], a1);
                a2 = fmaf(s.z, gw1[(d+2)*CNUM + t], a2);
                a3 = fmaf(s.w, gw1[(d+3)*CNUM + t], a3);
            }
            sh[t] = fmaxf((a0+a1)+(a2+a3) + gb1[t], 0.f);
        }
        __syncthreads();
        {
            float a0=0,a1=0,a2=0,a3=0;
            for (int j = 0; j < CNUM; j += 4) {
                float4 s = *reinterpret_cast<const float4*>(&sh[j]);
                a0 = fmaf(s.x, gw2[(j+0)*CNUM + t], a0);
                a1 = fmaf(s.y, gw2[(j+1)*CNUM + t], a1);
                a2 = fmaf(s.z, gw2[(j+2)*CNUM + t], a2);
                a3 = fmaf(s.w, gw2[(j+3)*CNUM + t], a3);
            }
            g_scale[b*CNUM + t] = 1.f + (a0+a1)+(a2+a3) + gb2[t];
        }
        __syncthreads();
        // beta
        {
            float a0=0,a1=0,a2=0,a3=0;
            for (int d = 0; d < DT; d += 4) {
                float4 s = *reinterpret_cast<const float4*>(&ss[d]);
                a0 = fmaf(s.x, bw1[(d+0)*CNUM + t], a0);
                a1 = fmaf(s.y, bw1[(d+1)*CNUM + t], a1);
                a2 = fmaf(s.z, bw1[(d+2)*CNUM + t], a2);
                a3 = fmaf(s.w, bw1[(d+3)*CNUM + t], a3);
            }
            sh[t] = fmaxf((a0+a1)+(a2+a3) + bb1[t], 0.f);
        }
        __syncthreads();
        {
            float a0=0,a1=0,a2=0,a3=0;
            for (int j = 0; j < CNUM; j += 4) {
                float4 s = *reinterpret_cast<const float4*>(&sh[j]);
                a0 = fmaf(s.x, bw2[(j+0)*CNUM + t], a0);
                a1 = fmaf(s.y, bw2[(j+1)*CNUM + t], a1);
                a2 = fmaf(s.z, bw2[(j+2)*CNUM + t], a2);
                a3 = fmaf(s.w, bw2[(j+3)*CNUM + t], a3);
            }
            g_beta[b*CNUM + t] = (a0+a1)+(a2+a3) + bb2[t];
        }
        __syncthreads();
        // direction vec2
        if (t < 64) {
            float a0=0,a1=0,a2=0,a3=0;
            for (int d = 0; d < DT; d += 4) {
                float4 s = *reinterpret_cast<const float4*>(&ss[d]);
                a0 = fmaf(s.x, dw1[(d+0)*64 + t], a0);
                a1 = fmaf(s.y, dw1[(d+1)*64 + t], a1);
                a2 = fmaf(s.z, dw1[(d+2)*64 + t], a2);
                a3 = fmaf(s.w, dw1[(d+3)*64 + t], a3);
            }
            sh[t] = fmaxf((a0+a1)+(a2+a3) + db1[t], 0.f);
        }
        __syncthreads();
        if (t == 0) {
            float v0 = db2[0], v1 = db2[1];
            for (int j = 0; j < 64; ++j) {
                v0 = fmaf(sh[j], dw2[j*2 + 0], v0);
                v1 = fmaf(sh[j], dw2[j*2 + 1], v1);
            }
            float nrm = fmaxf(sqrtf(v0*v0 + v1*v1), 1e-12f);
            g_vec2[b*2 + 0] = v0 / nrm;
            g_vec2[b*2 + 1] = v1 / nrm;
        }
    }
}

// ================= M = (K @ Wq)/16, tiled: 40 blocks of 8 rows =================
__global__ __launch_bounds__(256) void m_kernel(const float* __restrict__ Wq) {
    __shared__ __align__(16) float sK[KV_ROWS*CNUM];
    int t = threadIdx.x;
    int r0 = blockIdx.x * KV_ROWS;
    for (int i = t; i < KV_ROWS*CNUM; i += 256) sK[i] = g_K[r0*CNUM + i];
    __syncthreads();
    float acc[KV_ROWS];
#pragma unroll
    for (int r = 0; r < KV_ROWS; ++r) acc[r] = 0.f;
    int c = t;
    for (int o = 0; o < CNUM; o += 4) {
        float q0 = Wq[(o+0)*CNUM + c], q1 = Wq[(o+1)*CNUM + c];
        float q2 = Wq[(o+2)*CNUM + c], q3 = Wq[(o+3)*CNUM + c];
#pragma unroll
        for (int r = 0; r < KV_ROWS; ++r) {
            float4 k = *reinterpret_cast<const float4*>(&sK[r*CNUM + o]);
            acc[r] = fmaf(k.x, q0, acc[r]); acc[r] = fmaf(k.y, q1, acc[r]);
            acc[r] = fmaf(k.z, q2, acc[r]); acc[r] = fmaf(k.w, q3, acc[r]);
        }
    }
#pragma unroll
    for (int r = 0; r < KV_ROWS; ++r)
        g_M[(r0 + r)*CNUM + c] = acc[r] * 0.0625f;
}

// ---------------- block decode: 688 blocks, 512 pixels each ----------------
__device__ __forceinline__ void decode_block(int bid, int& level, int& b, int& tile) {
    if (bid < 512)      { level = 0; b = bid >> 5; tile = bid & 31; }
    else if (bid < 640) { int r = bid - 512; level = 1; b = r >> 3; tile = r & 7; }
    else if (bid < 672) { int r = bid - 640; level = 2; b = r >> 1; tile = r & 1; }
    else                { level = 3; b = bid - 672; tile = 0; }
}

// ================= Phase A: gate (2 pixels per thread) =================
__global__ __launch_bounds__(256, 2) void phaseA(const float* __restrict__ f0,
                                                 const float* __restrict__ f1,
                                                 const float* __restrict__ f2,
                                                 const float* __restrict__ f3,
                                                 const int* __restrict__ mask) {
    __shared__ __align__(16) float sM[LNUM*CNUM];
    __shared__ __align__(16) float sV[LNUM*CNUM];
    __shared__ int smask[LNUM];

    int level, b, tile;
    decode_block(blockIdx.x, level, b, tile);
    int t = threadIdx.x;
    int bbase = b * LNUM * CNUM;
    for (int i = t; i < LNUM*CNUM; i += 256) {
        sM[i] = g_M[bbase + i];
        sV[i] = g_V[bbase + i];
    }
    if (t < LNUM) smask[t] = mask[b*LNUM + t];
    __syncthreads();

    const int HW = c_HW[level];
    int n0 = tile * 512 + t;
    int n1 = n0 + 256;
    bool p1 = (n1 < HW);
    const float* fp = (level == 0) ? f0 : (level == 1) ? f1 : (level == 2) ? f2 : f3;
    fp += (size_t)(b * CNUM) * HW;

    unsigned long long acc0[LNUM], acc1[LNUM];
#pragma unroll
    for (int l = 0; l < LNUM; ++l) { acc0[l] = 0ull; acc1[l] = 0ull; }

    for (int c = 0; c < CNUM; c += 4) {
        const float* col = fp + (size_t)c * HW;
        float a0 = col[n0];
        float a1 = col[HW   + n0];
        float a2 = col[2*HW + n0];
        float a3 = col[3*HW + n0];
        float b0 = p1 ? col[n1]        : 0.f;
        float b1 = p1 ? col[HW   + n1] : 0.f;
        float b2 = p1 ? col[2*HW + n1] : 0.f;
        float b3 = p1 ? col[3*HW + n1] : 0.f;
        unsigned long long fa01 = pk2(a0, a1), fa23 = pk2(a2, a3);
        unsigned long long fb01 = pk2(b0, b1), fb23 = pk2(b2, b3);
#pragma unroll
        for (int l = 0; l < LNUM; ++l) {
            const ulonglong2 m = *reinterpret_cast<const ulonglong2*>(&sM[l*CNUM + c]);
            fma2(acc0[l], fa01, m.x);
            fma2(acc0[l], fa23, m.y);
            fma2(acc1[l], fb01, m.x);
            fma2(acc1[l], fb23, m.y);
        }
    }
    float lg0[LNUM], lg1[LNUM];
#pragma unroll
    for (int l = 0; l < LNUM; ++l) {
        float2 u0 = unpk2(acc0[l]); lg0[l] = u0.x + u0.y;
        float2 u1 = unpk2(acc1[l]); lg1[l] = u1.x + u1.y;
    }

    // masked softmax (both pixels)
    float mx0 = -1e30f, mx1 = -1e30f;
#pragma unroll
    for (int l = 0; l < LNUM; ++l) if (smask[l]) { mx0 = fmaxf(mx0, lg0[l]); mx1 = fmaxf(mx1, lg1[l]); }
    float s0 = 0.f, s1 = 0.f;
#pragma unroll
    for (int l = 0; l < LNUM; ++l) {
        float e0 = smask[l] ? __expf(lg0[l] - mx0) : 0.f;
        float e1 = smask[l] ? __expf(lg1[l] - mx1) : 0.f;
        lg0[l] = e0; s0 += e0;
        lg1[l] = e1; s1 += e1;
    }
    float inv0 = __fdividef(1.f, s0), inv1 = __fdividef(1.f, s1);
    unsigned long long at0[LNUM], at1[LNUM];
#pragma unroll
    for (int l = 0; l < LNUM; ++l) {
        float a0 = lg0[l] * inv0; at0[l] = pk2(a0, a0);
        float a1 = lg1[l] * inv1; at1[l] = pk2(a1, a1);
    }

    // gate = || attn @ V ||
    float gsq0 = 0.f, gsq1 = 0.f;
    for (int c = 0; c < CNUM; c += 4) {
        unsigned long long g01_0 = 0ull, g23_0 = 0ull, g01_1 = 0ull, g23_1 = 0ull;
#pragma unroll
        for (int l = 0; l < LNUM; ++l) {
            const ulonglong2 v = *reinterpret_cast<const ulonglong2*>(&sV[l*CNUM + c]);
            fma2(g01_0, at0[l], v.x);
            fma2(g23_0, at0[l], v.y);
            fma2(g01_1, at1[l], v.x);
            fma2(g23_1, at1[l], v.y);
        }
        float2 u = unpk2(g01_0), w = unpk2(g23_0);
        gsq0 = fmaf(u.x, u.x, gsq0); gsq0 = fmaf(u.y, u.y, gsq0);
        gsq0 = fmaf(w.x, w.x, gsq0); gsq0 = fmaf(w.y, w.y, gsq0);
        float2 u1v = unpk2(g01_1), w1v = unpk2(g23_1);
        gsq1 = fmaf(u1v.x, u1v.x, gsq1); gsq1 = fmaf(u1v.y, u1v.y, gsq1);
        gsq1 = fmaf(w1v.x, w1v.x, gsq1); gsq1 = fmaf(w1v.y, w1v.y, gsq1);
    }
    float gate0 = sqrtf(gsq0);
    int pbase = c_pixBase[level] + b*HW;
    g_gate_raw[pbase + n0] = gate0;
    atomicMax(&g_maxbuf[level*16 + b], __float_as_int(gate0));
    if (p1) {
        float gate1 = sqrtf(gsq1);
        g_gate_raw[pbase + n1] = gate1;
        atomicMax(&g_maxbuf[level*16 + b], __float_as_int(gate1));
    }
}

// ================= Phase A2 =================
__global__ __launch_bounds__(256) void phaseA2(float* __restrict__ out) {
    int level, b, tile;
    decode_block(blockIdx.x, level, b, tile);
    int t = threadIdx.x;
    const int HW = c_HW[level];
    const int W  = c_W[level];
    const int lw = c_lw[level];
    float step = c_step[level];
    float v0 = g_vec2[2*b], v1 = g_vec2[2*b + 1];
    float mxv = __int_as_float(g_maxbuf[level*16 + b]) + 1e-6f;
    int pbase = c_pixBase[level] + b*HW;
    int obase = c_gateOut[level] + b*HW;
#pragma unroll
    for (int p = 0; p < 2; ++p) {
        int n = tile * 512 + t + p * 256;
        if (n >= HW) break;
        int w = n & (W - 1);
        int h = n >> lw;
        float x = fmaf((float)w, step, -1.f);
        float y = fmaf((float)h, step, -1.f);
        float pr = v0 * x + v1 * y;
        float di = __fdividef(1.f, 1.f + __expf(-pr));
        float gi = __fdividef(g_gate_raw[pbase + n], mxv) * di;
        g_gi[pbase + n] = gi;
        out[obase + n] = gi;
    }
}

// ================= Phase B =================
__global__ __launch_bounds__(256) void phaseB(const float* __restrict__ f0,
                                              const float* __restrict__ f1,
                                              const float* __restrict__ f2,
                                              const float* __restrict__ f3,
                                              float* __restrict__ out) {
    int g4 = blockIdx.x * 256 + threadIdx.x;
    int level, idx;
    if (g4 < 16777216)      { level = 0; idx = g4; }
    else if (g4 < 20971520) { level = 1; idx = g4 - 16777216; }
    else if (g4 < 22020096) { level = 2; idx = g4 - 20971520; }
    else                    { level = 3; idx = g4 - 22020096; }
    const int HW   = c_HW[level];
    const int lHW4 = c_lHW4[level];
    int n4   = idx & ((HW >> 2) - 1);
    int rest = idx >> lHW4;
    int c = rest & 255;
    int b = rest >> 8;
    int n = n4 << 2;

    const float* fp = (level == 0) ? f0 : (level == 1) ? f1 : (level == 2) ? f2 : f3;
    const float4 f  = *reinterpret_cast<const float4*>(fp + (size_t)(b*CNUM + c)*HW + n);
    const float4 gi = *reinterpret_cast<const float4*>(&g_gi[c_pixBase[level] + b*HW + n]);
    float sc = g_scale[b*CNUM + c];
    float be = g_beta[b*CNUM + c];
    float4 o;
    o.x = fmaf(gi.x * f.x, sc, be);
    o.y = fmaf(gi.y * f.y, sc, be);
    o.z = fmaf(gi.z * f.z, sc, be);
    o.w = fmaf(gi.w * f.w, sc, be);
    *reinterpret_cast<float4*>(out + (size_t)g4 * 4) = o;
}

// ================= launch =================
extern "C" void kernel_launch(void* const* d_in, const int* in_sizes, int n_in,
                              void* d_out, int out_size) {
    const float* f0   = (const float*)d_in[0];
    const float* f1   = (const float*)d_in[1];
    const float* f2   = (const float*)d_in[2];
    const float* f3   = (const float*)d_in[3];
    const float* wt   = (const float*)d_in[4];
    const float* sent = (const float*)d_in[5];
    const int*   mask = (const int*)  d_in[6];
    const float* Wq   = (const float*)d_in[7];
    const float* Wk   = (const float*)d_in[8];
    const float* Wv   = (const float*)d_in[9];
    const float* gw1  = (const float*)d_in[10];
    const float* gb1  = (const float*)d_in[11];
    const float* gw2  = (const float*)d_in[12];
    const float* gb2  = (const float*)d_in[13];
    const float* bw1  = (const float*)d_in[14];
    const float* bb1  = (const float*)d_in[15];
    const float* bw2  = (const float*)d_in[16];
    const float* bb2  = (const float*)d_in[17];
    const float* dw1  = (const float*)d_in[18];
    const float* db1  = (const float*)d_in[19];
    const float* dw2  = (const float*)d_in[20];
    const float* db2  = (const float*)d_in[21];
    float* out = (float*)d_out;

    prep_kernel<<<56, 256>>>(wt, Wk, Wv, sent, gw1, gb1, gw2, gb2,
                             bw1, bb1, bw2, bb2, dw1, db1, dw2, db2);
    m_kernel<<<40, 256>>>(Wq);
    phaseA<<<688, 256>>>(f0, f1, f2, f3, mask);
    phaseA2<<<688, 256>>>(out);
    phaseB<<<87040, 256>>>(f0, f1, f2, f3, out);
}

// round 3
// speedup vs baseline: 1.1627x; 1.0247x over previous
#include <cuda_runtime.h>
#include <math.h>

#define BNUM 16
#define LNUM 20
#define CNUM 256
#define DT   768

// ---------------- scratch ----------------
__device__ float g_K[BNUM*LNUM*CNUM];
__device__ float g_V[BNUM*LNUM*CNUM];
__device__ float g_M[BNUM*LNUM*CNUM];
__device__ float g_G[BNUM*LNUM*LNUM];     // V @ V^T per batch
__device__ float g_scale[BNUM*CNUM];
__device__ float g_beta[BNUM*CNUM];
__device__ float g_vec2[BNUM*2];
__device__ int   g_maxbuf[64];
__device__ __align__(16) float g_gate_raw[348160];
__device__ __align__(16) float g_gi[348160];

// ---------------- per-level constants ----------------
__constant__ int   c_HW[4]      = {16384, 4096, 1024, 256};
__constant__ int   c_W[4]       = {128, 64, 32, 16};
__constant__ int   c_lw[4]      = {7, 6, 5, 4};
__constant__ int   c_lHW4[4]    = {12, 10, 8, 6};
__constant__ int   c_pixBase[4] = {0, 262144, 327680, 344064};
__constant__ int   c_gateOut[4] = {89128960, 89391104, 89456640, 89473024};
__constant__ float c_step[4]    = {2.f/127.f, 2.f/63.f, 2.f/31.f, 2.f/15.f};

// ---------------- packed f32x2 helpers ----------------
__device__ __forceinline__ unsigned long long pk2(float lo, float hi) {
    unsigned long long r;
    asm("mov.b64 %0,{%1,%2};" : "=l"(r) : "f"(lo), "f"(hi));
    return r;
}
__device__ __forceinline__ void fma2(unsigned long long& d, unsigned long long a, unsigned long long b) {
    asm("fma.rn.f32x2 %0,%1,%2,%0;" : "+l"(d) : "l"(a), "l"(b));
}
__device__ __forceinline__ float2 unpk2(unsigned long long v) {
    float2 f;
    asm("mov.b64 {%0,%1},%2;" : "=f"(f.x), "=f"(f.y) : "l"(v));
    return f;
}

// ================= prep: blocks 0..39 = KV tiles; 40..55 = mod MLPs =================
#define KV_ROWS 8
__global__ __launch_bounds__(256) void prep_kernel(
    const float* __restrict__ wt, const float* __restrict__ Wk, const float* __restrict__ Wv,
    const float* __restrict__ sent,
    const float* __restrict__ gw1, const float* __restrict__ gb1,
    const float* __restrict__ gw2, const float* __restrict__ gb2,
    const float* __restrict__ bw1, const float* __restrict__ bb1,
    const float* __restrict__ bw2, const float* __restrict__ bb2,
    const float* __restrict__ dw1, const float* __restrict__ db1,
    const float* __restrict__ dw2, const float* __restrict__ db2)
{
    __shared__ __align__(16) float swt[KV_ROWS*DT];
    __shared__ __align__(16) float ss[DT];
    __shared__ float sh[CNUM];
    int t = threadIdx.x;
    int bid = blockIdx.x;

    if (bid < 40) {
        if (bid == 0 && t < 64) g_maxbuf[t] = 0;
        int r0 = bid * KV_ROWS;
        for (int i = t; i < KV_ROWS*DT; i += 256) swt[i] = wt[(size_t)r0*DT + i];
        __syncthreads();
        float aK[KV_ROWS], aV[KV_ROWS];
#pragma unroll
        for (int r = 0; r < KV_ROWS; ++r) { aK[r] = 0.f; aV[r] = 0.f; }
        int c = t;
        for (int d = 0; d < DT; d += 4) {
            float k0 = Wk[(d+0)*CNUM + c], k1 = Wk[(d+1)*CNUM + c];
            float k2 = Wk[(d+2)*CNUM + c], k3 = Wk[(d+3)*CNUM + c];
            float v0 = Wv[(d+0)*CNUM + c], v1 = Wv[(d+1)*CNUM + c];
            float v2 = Wv[(d+2)*CNUM + c], v3 = Wv[(d+3)*CNUM + c];
#pragma unroll
            for (int r = 0; r < KV_ROWS; ++r) {
                float4 w = *reinterpret_cast<const float4*>(&swt[r*DT + d]);
                aK[r] = fmaf(w.x, k0, aK[r]); aK[r] = fmaf(w.y, k1, aK[r]);
                aK[r] = fmaf(w.z, k2, aK[r]); aK[r] = fmaf(w.w, k3, aK[r]);
                aV[r] = fmaf(w.x, v0, aV[r]); aV[r] = fmaf(w.y, v1, aV[r]);
                aV[r] = fmaf(w.z, v2, aV[r]); aV[r] = fmaf(w.w, v3, aV[r]);
            }
        }
#pragma unroll
        for (int r = 0; r < KV_ROWS; ++r) {
            g_K[(r0 + r)*CNUM + c] = aK[r];
            g_V[(r0 + r)*CNUM + c] = aV[r];
        }
    } else {
        int b = bid - 40;
        for (int i = t; i < DT; i += 256) ss[i] = sent[b*DT + i];
        __syncthreads();
        {
            float a0=0,a1=0,a2=0,a3=0;
            for (int d = 0; d < DT; d += 4) {
                float4 s = *reinterpret_cast<const float4*>(&ss[d]);
                a0 = fmaf(s.x, gw1[(d+0)*CNUM + t], a0);
                a1 = fmaf(s.y, gw1[(d+1)*CNUM + t], a1);
                a2 = fmaf(s.z, gw1[(d+2)*CNUM + t], a2);
                a3 = fmaf(s.w, gw1[(d+3)*CNUM + t], a3);
            }
            sh[t] = fmaxf((a0+a1)+(a2+a3) + gb1[t], 0.f);
        }
        __syncthreads();
        {
            float a0=0,a1=0,a2=0,a3=0;
            for (int j = 0; j < CNUM; j += 4) {
                float4 s = *reinterpret_cast<const float4*>(&sh[j]);
                a0 = fmaf(s.x, gw2[(j+0)*CNUM + t], a0);
                a1 = fmaf(s.y, gw2[(j+1)*CNUM + t], a1);
                a2 = fmaf(s.z, gw2[(j+2)*CNUM + t], a2);
                a3 = fmaf(s.w, gw2[(j+3)*CNUM + t], a3);
            }
            g_scale[b*CNUM + t] = 1.f + (a0+a1)+(a2+a3) + gb2[t];
        }
        __syncthreads();
        {
            float a0=0,a1=0,a2=0,a3=0;
            for (int d = 0; d < DT; d += 4) {
                float4 s = *reinterpret_cast<const float4*>(&ss[d]);
                a0 = fmaf(s.x, bw1[(d+0)*CNUM + t], a0);
                a1 = fmaf(s.y, bw1[(d+1)*CNUM + t], a1);
                a2 = fmaf(s.z, bw1[(d+2)*CNUM + t], a2);
                a3 = fmaf(s.w, bw1[(d+3)*CNUM + t], a3);
            }
            sh[t] = fmaxf((a0+a1)+(a2+a3) + bb1[t], 0.f);
        }
        __syncthreads();
        {
            float a0=0,a1=0,a2=0,a3=0;
            for (int j = 0; j < CNUM; j += 4) {
                float4 s = *reinterpret_cast<const float4*>(&sh[j]);
                a0 = fmaf(s.x, bw2[(j+0)*CNUM + t], a0);
                a1 = fmaf(s.y, bw2[(j+1)*CNUM + t], a1);
                a2 = fmaf(s.z, bw2[(j+2)*CNUM + t], a2);
                a3 = fmaf(s.w, bw2[(j+3)*CNUM + t], a3);
            }
            g_beta[b*CNUM + t] = (a0+a1)+(a2+a3) + bb2[t];
        }
        __syncthreads();
        if (t < 64) {
            float a0=0,a1=0,a2=0,a3=0;
            for (int d = 0; d < DT; d += 4) {
                float4 s = *reinterpret_cast<const float4*>(&ss[d]);
                a0 = fmaf(s.x, dw1[(d+0)*64 + t], a0);
                a1 = fmaf(s.y, dw1[(d+1)*64 + t], a1);
                a2 = fmaf(s.z, dw1[(d+2)*64 + t], a2);
                a3 = fmaf(s.w, dw1[(d+3)*64 + t], a3);
            }
            sh[t] = fmaxf((a0+a1)+(a2+a3) + db1[t], 0.f);
        }
        __syncthreads();
        if (t == 0) {
            float v0 = db2[0], v1 = db2[1];
            for (int j = 0; j < 64; ++j) {
                v0 = fmaf(sh[j], dw2[j*2 + 0], v0);
                v1 = fmaf(sh[j], dw2[j*2 + 1], v1);
            }
            float nrm = fmaxf(sqrtf(v0*v0 + v1*v1), 1e-12f);
            g_vec2[b*2 + 0] = v0 / nrm;
            g_vec2[b*2 + 1] = v1 / nrm;
        }
    }
}

// ================= blocks 0..39: M = (K@Wq)/16; blocks 40..55: G = V@V^T =================
__global__ __launch_bounds__(256) void m_kernel(const float* __restrict__ Wq) {
    __shared__ __align__(16) float sK[KV_ROWS*CNUM];   // also reused for V (20KB case below)
    int t = threadIdx.x;
    int bid = blockIdx.x;
    if (bid < 40) {
        int r0 = bid * KV_ROWS;
        for (int i = t; i < KV_ROWS*CNUM; i += 256) sK[i] = g_K[r0*CNUM + i];
        __syncthreads();
        float acc[KV_ROWS];
#pragma unroll
        for (int r = 0; r < KV_ROWS; ++r) acc[r] = 0.f;
        int c = t;
        for (int o = 0; o < CNUM; o += 4) {
            float q0 = Wq[(o+0)*CNUM + c], q1 = Wq[(o+1)*CNUM + c];
            float q2 = Wq[(o+2)*CNUM + c], q3 = Wq[(o+3)*CNUM + c];
#pragma unroll
            for (int r = 0; r < KV_ROWS; ++r) {
                float4 k = *reinterpret_cast<const float4*>(&sK[r*CNUM + o]);
                acc[r] = fmaf(k.x, q0, acc[r]); acc[r] = fmaf(k.y, q1, acc[r]);
                acc[r] = fmaf(k.z, q2, acc[r]); acc[r] = fmaf(k.w, q3, acc[r]);
            }
        }
#pragma unroll
        for (int r = 0; r < KV_ROWS; ++r)
            g_M[(r0 + r)*CNUM + c] = acc[r] * 0.0625f;
    }
}

__global__ __launch_bounds__(256) void vvt_kernel() {
    __shared__ __align__(16) float sV[LNUM*CNUM];   // 20KB
    int b = blockIdx.x, t = threadIdx.x;
    for (int i = t; i < LNUM*CNUM; i += 256) sV[i] = g_V[b*LNUM*CNUM + i];
    __syncthreads();
    for (int e = t; e < LNUM*LNUM; e += 256) {
        int l  = e / LNUM;
        int l2 = e % LNUM;
        float a0=0,a1=0,a2=0,a3=0;
        for (int c = 0; c < CNUM; c += 4) {
            float4 x = *reinterpret_cast<const float4*>(&sV[l*CNUM + c]);
            float4 y = *reinterpret_cast<const float4*>(&sV[l2*CNUM + c]);
            a0 = fmaf(x.x, y.x, a0); a1 = fmaf(x.y, y.y, a1);
            a2 = fmaf(x.z, y.z, a2); a3 = fmaf(x.w, y.w, a3);
        }
        g_G[b*LNUM*LNUM + e] = (a0+a1)+(a2+a3);
    }
}

// ---------------- block decode: 688 blocks, 512 pixels each ----------------
__device__ __forceinline__ void decode_block(int bid, int& level, int& b, int& tile) {
    if (bid < 512)      { level = 0; b = bid >> 5; tile = bid & 31; }
    else if (bid < 640) { int r = bid - 512; level = 1; b = r >> 3; tile = r & 7; }
    else if (bid < 672) { int r = bid - 640; level = 2; b = r >> 1; tile = r & 1; }
    else                { level = 3; b = bid - 672; tile = 0; }
}

// ================= Phase A: gate (2 adjacent pixels per thread, Gram trick) =================
__global__ __launch_bounds__(256, 2) void phaseA(const float* __restrict__ f0,
                                                 const float* __restrict__ f1,
                                                 const float* __restrict__ f2,
                                                 const float* __restrict__ f3,
                                                 const int* __restrict__ mask) {
    __shared__ __align__(16) float sM[LNUM*CNUM];                  // 20KB
    __shared__ __align__(16) unsigned long long sG2[LNUM*LNUM];    // packed (g,g), 3.2KB
    __shared__ int smask[LNUM];

    int level, b, tile;
    decode_block(blockIdx.x, level, b, tile);
    int t = threadIdx.x;
    int bbase = b * LNUM * CNUM;
    for (int i = t; i < LNUM*CNUM; i += 256) sM[i] = g_M[bbase + i];
    for (int i = t; i < LNUM*LNUM; i += 256) {
        float g = g_G[b*LNUM*LNUM + i];
        sG2[i] = pk2(g, g);
    }
    if (t < LNUM) smask[t] = mask[b*LNUM + t];
    __syncthreads();

    const int HW = c_HW[level];
    int n0 = tile * 512 + 2 * t;     // pixels n0, n0+1
    bool p0 = (n0 < HW);
    const float* fp = (level == 0) ? f0 : (level == 1) ? f1 : (level == 2) ? f2 : f3;
    fp += (size_t)(b * CNUM) * HW + n0;

    // logits: acc0 = pixel n0, acc1 = pixel n0+1 (each packed over channel pairs)
    unsigned long long acc0[LNUM], acc1[LNUM];
#pragma unroll
    for (int l = 0; l < LNUM; ++l) { acc0[l] = 0ull; acc1[l] = 0ull; }

    for (int c = 0; c < CNUM; c += 4) {
        const float* col = fp + (size_t)c * HW;
        float2 r0 = p0 ? *reinterpret_cast<const float2*>(col)          : make_float2(0.f, 0.f);
        float2 r1 = p0 ? *reinterpret_cast<const float2*>(col + HW)     : make_float2(0.f, 0.f);
        float2 r2 = p0 ? *reinterpret_cast<const float2*>(col + 2*HW)   : make_float2(0.f, 0.f);
        float2 r3 = p0 ? *reinterpret_cast<const float2*>(col + 3*HW)   : make_float2(0.f, 0.f);
        unsigned long long fa01 = pk2(r0.x, r1.x), fa23 = pk2(r2.x, r3.x);
        unsigned long long fb01 = pk2(r0.y, r1.y), fb23 = pk2(r2.y, r3.y);
#pragma unroll
        for (int l = 0; l < LNUM; ++l) {
            const ulonglong2 m = *reinterpret_cast<const ulonglong2*>(&sM[l*CNUM + c]);
            fma2(acc0[l], fa01, m.x);
            fma2(acc0[l], fa23, m.y);
            fma2(acc1[l], fb01, m.x);
            fma2(acc1[l], fb23, m.y);
        }
    }
    float lg0[LNUM], lg1[LNUM];
#pragma unroll
    for (int l = 0; l < LNUM; ++l) {
        float2 u0 = unpk2(acc0[l]); lg0[l] = u0.x + u0.y;
        float2 u1 = unpk2(acc1[l]); lg1[l] = u1.x + u1.y;
    }

    // masked softmax
    float mx0 = -1e30f, mx1 = -1e30f;
#pragma unroll
    for (int l = 0; l < LNUM; ++l) if (smask[l]) { mx0 = fmaxf(mx0, lg0[l]); mx1 = fmaxf(mx1, lg1[l]); }
    float s0 = 0.f, s1 = 0.f;
#pragma unroll
    for (int l = 0; l < LNUM; ++l) {
        float e0 = smask[l] ? __expf(lg0[l] - mx0) : 0.f;
        float e1 = smask[l] ? __expf(lg1[l] - mx1) : 0.f;
        lg0[l] = e0; s0 += e0;
        lg1[l] = e1; s1 += e1;
    }
    float inv0 = __fdividef(1.f, s0), inv1 = __fdividef(1.f, s1);
    unsigned long long ap[LNUM];     // attn packed over the 2 pixels
#pragma unroll
    for (int l = 0; l < LNUM; ++l) ap[l] = pk2(lg0[l] * inv0, lg1[l] * inv1);

    // gate^2 = a^T G a (packed over the pixel pair)
    unsigned long long gs = 0ull;
#pragma unroll
    for (int l = 0; l < LNUM; ++l) {
        unsigned long long tt = 0ull;
#pragma unroll
        for (int l2 = 0; l2 < LNUM; l2 += 2) {
            const ulonglong2 gg = *reinterpret_cast<const ulonglong2*>(&sG2[l*LNUM + l2]);
            fma2(tt, ap[l2],     gg.x);
            fma2(tt, ap[l2 + 1], gg.y);
        }
        fma2(gs, ap[l], tt);
    }
    if (p0) {
        float2 gu = unpk2(gs);
        float gate0 = sqrtf(gu.x);
        float gate1 = sqrtf(gu.y);
        int pbase = c_pixBase[level] + b*HW;
        *reinterpret_cast<float2*>(&g_gate_raw[pbase + n0]) = make_float2(gate0, gate1);
        atomicMax(&g_maxbuf[level*16 + b], __float_as_int(fmaxf(gate0, gate1)));
    }
}

// ================= Phase A2 =================
__global__ __launch_bounds__(256) void phaseA2(float* __restrict__ out) {
    int level, b, tile;
    decode_block(blockIdx.x, level, b, tile);
    int t = threadIdx.x;
    const int HW = c_HW[level];
    const int W  = c_W[level];
    const int lw = c_lw[level];
    float step = c_step[level];
    float v0 = g_vec2[2*b], v1 = g_vec2[2*b + 1];
    float mxv = __int_as_float(g_maxbuf[level*16 + b]) + 1e-6f;
    int pbase = c_pixBase[level] + b*HW;
    int obase = c_gateOut[level] + b*HW;
#pragma unroll
    for (int p = 0; p < 2; ++p) {
        int n = tile * 512 + t + p * 256;
        if (n >= HW) break;
        int w = n & (W - 1);
        int h = n >> lw;
        float x = fmaf((float)w, step, -1.f);
        float y = fmaf((float)h, step, -1.f);
        float pr = v0 * x + v1 * y;
        float di = __fdividef(1.f, 1.f + __expf(-pr));
        float gi = __fdividef(g_gate_raw[pbase + n], mxv) * di;
        g_gi[pbase + n] = gi;
        out[obase + n] = gi;
    }
}

// ================= Phase B: 2 float4 per thread =================
__device__ __forceinline__ void phaseB_one(int g4,
                                           const float* __restrict__ f0,
                                           const float* __restrict__ f1,
                                           const float* __restrict__ f2,
                                           const float* __restrict__ f3,
                                           float* __restrict__ out) {
    int level, idx;
    if (g4 < 16777216)      { level = 0; idx = g4; }
    else if (g4 < 20971520) { level = 1; idx = g4 - 16777216; }
    else if (g4 < 22020096) { level = 2; idx = g4 - 20971520; }
    else                    { level = 3; idx = g4 - 22020096; }
    const int HW   = c_HW[level];
    const int lHW4 = c_lHW4[level];
    int n4   = idx & ((HW >> 2) - 1);
    int rest = idx >> lHW4;
    int c = rest & 255;
    int b = rest >> 8;
    int n = n4 << 2;

    const float* fp = (level == 0) ? f0 : (level == 1) ? f1 : (level == 2) ? f2 : f3;
    const float4 f  = *reinterpret_cast<const float4*>(fp + (size_t)(b*CNUM + c)*HW + n);
    const float4 gi = *reinterpret_cast<const float4*>(&g_gi[c_pixBase[level] + b*HW + n]);
    float sc = g_scale[b*CNUM + c];
    float be = g_beta[b*CNUM + c];
    float4 o;
    o.x = fmaf(gi.x * f.x, sc, be);
    o.y = fmaf(gi.y * f.y, sc, be);
    o.z = fmaf(gi.z * f.z, sc, be);
    o.w = fmaf(gi.w * f.w, sc, be);
    *reinterpret_cast<float4*>(out + (size_t)g4 * 4) = o;
}

__global__ __launch_bounds__(256) void phaseB(const float* __restrict__ f0,
                                              const float* __restrict__ f1,
                                              const float* __restrict__ f2,
                                              const float* __restrict__ f3,
                                              float* __restrict__ out) {
    int base = blockIdx.x * 512 + threadIdx.x;
    phaseB_one(base,       f0, f1, f2, f3, out);
    phaseB_one(base + 256, f0, f1, f2, f3, out);
}

// ================= launch =================
extern "C" void kernel_launch(void* const* d_in, const int* in_sizes, int n_in,
                              void* d_out, int out_size) {
    const float* f0   = (const float*)d_in[0];
    const float* f1   = (const float*)d_in[1];
    const float* f2   = (const float*)d_in[2];
    const float* f3   = (const float*)d_in[3];
    const float* wt   = (const float*)d_in[4];
    const float* sent = (const float*)d_in[5];
    const int*   mask = (const int*)  d_in[6];
    const float* Wq   = (const float*)d_in[7];
    const float* Wk   = (const float*)d_in[8];
    const float* Wv   = (const float*)d_in[9];
    const float* gw1  = (const float*)d_in[10];
    const float* gb1  = (const float*)d_in[11];
    const float* gw2  = (const float*)d_in[12];
    const float* gb2  = (const float*)d_in[13];
    const float* bw1  = (const float*)d_in[14];
    const float* bb1  = (const float*)d_in[15];
    const float* bw2  = (const float*)d_in[16];
    const float* bb2  = (const float*)d_in[17];
    const float* dw1  = (const float*)d_in[18];
    const float* db1  = (const float*)d_in[19];
    const float* dw2  = (const float*)d_in[20];
    const float* db2  = (const float*)d_in[21];
    float* out = (float*)d_out;

    prep_kernel<<<56, 256>>>(wt, Wk, Wv, sent, gw1, gb1, gw2, gb2,
                             bw1, bb1, bw2, bb2, dw1, db1, dw2, db2);
    m_kernel<<<40, 256>>>(Wq);
    vvt_kernel<<<16, 256>>>();
    phaseA<<<688, 256>>>(f0, f1, f2, f3, mask);
    phaseA2<<<688, 256>>>(out);
    phaseB<<<43520, 256>>>(f0, f1, f2, f3, out);
}